// round 7
// baseline (speedup 1.0000x reference)
#include <cuda_runtime.h>
#include <cstdint>

#define CIN   32
#define COUT  64
#define EPS   1e-4f
#define LEAK  0.333f

#define HB           256           // hist/scatter blocks
#define N_MAX        1600000
#define CONV_BLOCKS  1184
#define STATS_BLOCKS 1184

__device__ int   g_blockhist[4 * HB];
__device__ int   g_blockoff[4 * HB];
__device__ int   g_bucket_start[5];
__device__ int   g_perm[N_MAX];
__device__ float g_partials[STATS_BLOCKS * 128];
__device__ float g_coef[128];

// ---- packed f32x2 helpers (sm_103a) ---------------------------------------
__device__ __forceinline__ unsigned long long pack2(float x) {
    unsigned long long r;
    asm("mov.b64 %0, {%1, %1};" : "=l"(r) : "f"(x));
    return r;
}
__device__ __forceinline__ unsigned long long ffma2(unsigned long long a,
                                                    unsigned long long b,
                                                    unsigned long long c) {
    unsigned long long d;
    asm("fma.rn.f32x2 %0, %1, %2, %3;" : "=l"(d) : "l"(a), "l"(b), "l"(c));
    return d;
}
__device__ __forceinline__ void unpack2(unsigned long long v, float& lo, float& hi) {
    asm("mov.b64 {%0, %1}, %2;" : "=f"(lo), "=f"(hi) : "l"(v));
}

// ---- sort pass 1: per-block histogram of kern_idx --------------------------
__global__ __launch_bounds__(256) void hist_kernel(const int* __restrict__ kern_idx,
                                                   int n_rows)
{
    __shared__ int cnt[4];
    if (threadIdx.x < 4) cnt[threadIdx.x] = 0;
    __syncthreads();
    int chunk = (n_rows + HB - 1) / HB;
    int i0 = blockIdx.x * chunk;
    int i1 = min(i0 + chunk, n_rows);
    int c[4] = {0, 0, 0, 0};
    for (int i = i0 + threadIdx.x; i < i1; i += 256) c[kern_idx[i]]++;
    #pragma unroll
    for (int kk = 0; kk < 4; kk++)
        if (c[kk]) atomicAdd(&cnt[kk], c[kk]);
    __syncthreads();
    if (threadIdx.x < 4)
        g_blockhist[threadIdx.x * HB + blockIdx.x] = cnt[threadIdx.x];
}

// ---- sort pass 2: segmented scan -> per-block offsets + bucket starts ------
__global__ void scan_kernel(int n_rows)
{
    __shared__ int sh[4 * HB];
    int t = threadIdx.x;            // 0..1023, t = k*256 + b
    int orig = g_blockhist[t];
    sh[t] = orig;
    __syncthreads();
    for (int s = 1; s < HB; s <<= 1) {
        int add = ((t & (HB - 1)) >= s) ? sh[t - s] : 0;
        __syncthreads();
        sh[t] += add;
        __syncthreads();
    }
    int k = t >> 8;
    int kbase = 0;
    for (int kk = 0; kk < k; kk++) kbase += sh[kk * HB + HB - 1];
    g_blockoff[t] = kbase + (sh[t] - orig);
    if ((t & (HB - 1)) == 0) g_bucket_start[k] = kbase;
    if (t == 0) g_bucket_start[4] = n_rows;
}

// ---- sort pass 3: scatter row indices into buckets -------------------------
__global__ __launch_bounds__(256) void scatter_kernel(const int* __restrict__ kern_idx,
                                                      int n_rows)
{
    __shared__ int scur[4];
    if (threadIdx.x < 4)
        scur[threadIdx.x] = g_blockoff[threadIdx.x * HB + blockIdx.x];
    __syncthreads();
    int chunk = (n_rows + HB - 1) / HB;
    int i0 = blockIdx.x * chunk;
    int i1 = min(i0 + chunk, n_rows);
    int iters = (i1 > i0) ? ((i1 - i0 + 255) >> 8) : 0;
    int lane = threadIdx.x & 31;
    for (int it = 0; it < iters; it++) {
        int i = i0 + it * 256 + threadIdx.x;
        int k = (i < i1) ? kern_idx[i] : -1;
        #pragma unroll
        for (int kk = 0; kk < 4; kk++) {
            unsigned mask = __ballot_sync(0xFFFFFFFFu, k == kk);
            if (k == kk) {
                int leader = __ffs(mask) - 1;
                int base = 0;
                if (lane == leader) base = atomicAdd(&scur[kk], __popc(mask));
                base = __shfl_sync(mask, base, leader);
                int pos = base + __popc(mask & ((1u << lane) - 1));
                g_perm[pos] = i;
            }
        }
    }
}

// ---- conv: warp-per-row, weights in registers (per-bucket warps) -----------
// lane l owns channels {2l,2l+1}; its 32 weight pairs for bucket k live in
// 32 ull regs. Per row: 3 LDG + 32 SHFL + 32 FFMA2 (2 chains) + 1 RED.64.
__global__ __launch_bounds__(256) void conv_scatter(
    const float* __restrict__ feat,
    const float* __restrict__ weight,
    const int*   __restrict__ out_idx,
    float*       __restrict__ out,
    int n_rows)
{
    int lane  = threadIdx.x & 31;
    int gw    = (blockIdx.x * blockDim.x + threadIdx.x) >> 5;
    int k     = gw & 3;
    int wslot = gw >> 2;
    int nwb   = (gridDim.x * blockDim.x) >> 7;   // warps per bucket

    unsigned long long wreg[32];
    #pragma unroll
    for (int j = 0; j < 32; j++)
        wreg[j] = *reinterpret_cast<const unsigned long long*>(
            weight + ((size_t)(k * 32 + j) * 64 + 2 * lane));

    int start = g_bucket_start[k];
    int end   = g_bucket_start[k + 1];

    for (int p = start + wslot; p < end; p += nwb) {
        int i = g_perm[p];                       // warp-uniform broadcast load
        int o = out_idx[i];                      // warp-uniform broadcast load
        float f = feat[(size_t)i * CIN + lane];  // coalesced: 1 line/warp

        unsigned long long a0 = 0ull, a1 = 0ull;
        #pragma unroll
        for (int j = 0; j < 32; j += 2) {
            float fa = __shfl_sync(0xFFFFFFFFu, f, j);
            float fb = __shfl_sync(0xFFFFFFFFu, f, j + 1);
            a0 = ffma2(wreg[j],     pack2(fa), a0);
            a1 = ffma2(wreg[j + 1], pack2(fb), a1);
        }
        unsigned long long acc;
        asm("add.rn.f32x2 %0, %1, %2;" : "=l"(acc) : "l"(a0), "l"(a1));
        float lo, hi;
        unpack2(acc, lo, hi);
        atomicAdd(reinterpret_cast<float2*>(out + (size_t)o * COUT + 2 * lane),
                  make_float2(lo, hi));          // warp: 256B contiguous RED.64
    }
}

// ---- stats: per-channel sum / sumsq partials -------------------------------
__global__ __launch_bounds__(256) void stats_kernel(const float* __restrict__ out,
                                                    int n_out)
{
    __shared__ float sh[128];
    if (threadIdx.x < 128) sh[threadIdx.x] = 0.f;
    __syncthreads();

    int gid = blockIdx.x * blockDim.x + threadIdx.x;
    int c4 = threadIdx.x & 15;
    int row0 = gid >> 4;
    int rstride = (gridDim.x * blockDim.x) >> 4;
    const float4* o4 = reinterpret_cast<const float4*>(out);

    float4 s = make_float4(0.f, 0.f, 0.f, 0.f);
    float4 q = make_float4(0.f, 0.f, 0.f, 0.f);
    for (int r = row0; r < n_out; r += rstride) {
        float4 v = o4[(size_t)r * 16 + c4];
        s.x += v.x; s.y += v.y; s.z += v.z; s.w += v.w;
        q.x += v.x * v.x; q.y += v.y * v.y; q.z += v.z * v.z; q.w += v.w * v.w;
    }
    s.x += __shfl_down_sync(0xFFFFFFFFu, s.x, 16);
    s.y += __shfl_down_sync(0xFFFFFFFFu, s.y, 16);
    s.z += __shfl_down_sync(0xFFFFFFFFu, s.z, 16);
    s.w += __shfl_down_sync(0xFFFFFFFFu, s.w, 16);
    q.x += __shfl_down_sync(0xFFFFFFFFu, q.x, 16);
    q.y += __shfl_down_sync(0xFFFFFFFFu, q.y, 16);
    q.z += __shfl_down_sync(0xFFFFFFFFu, q.z, 16);
    q.w += __shfl_down_sync(0xFFFFFFFFu, q.w, 16);

    if ((threadIdx.x & 31) < 16) {
        atomicAdd(&sh[c4 * 4 + 0], s.x);
        atomicAdd(&sh[c4 * 4 + 1], s.y);
        atomicAdd(&sh[c4 * 4 + 2], s.z);
        atomicAdd(&sh[c4 * 4 + 3], s.w);
        atomicAdd(&sh[64 + c4 * 4 + 0], q.x);
        atomicAdd(&sh[64 + c4 * 4 + 1], q.y);
        atomicAdd(&sh[64 + c4 * 4 + 2], q.z);
        atomicAdd(&sh[64 + c4 * 4 + 3], q.w);
    }
    __syncthreads();
    if (threadIdx.x < 128)
        g_partials[blockIdx.x * 128 + threadIdx.x] = sh[threadIdx.x];
}

// ---- coef: reduce partials -> per-channel A,B ------------------------------
__global__ void coef_kernel(const float* __restrict__ gamma,
                            const float* __restrict__ beta,
                            int n_out)
{
    int t = threadIdx.x;   // 0..127
    float acc = 0.f;
    #pragma unroll 8
    for (int b = 0; b < STATS_BLOCKS; b++)
        acc += g_partials[b * 128 + t];
    __shared__ float tot[128];
    tot[t] = acc;
    __syncthreads();
    if (t < 64) {
        float inv_n = 1.0f / (float)n_out;
        float mean = tot[t] * inv_n;
        float var  = tot[64 + t] * inv_n - mean * mean;
        float A = gamma[t] * rsqrtf(var + EPS);
        float B = beta[t] - mean * A;
        g_coef[t] = A;
        g_coef[64 + t] = B;
    }
}

// ---- norm + leaky relu (in place, at DRAM roofline) ------------------------
__global__ __launch_bounds__(256) void norm_kernel(float* __restrict__ out, int n_out)
{
    int gid = blockIdx.x * blockDim.x + threadIdx.x;
    int c4 = threadIdx.x & 15;
    const float4* cf = reinterpret_cast<const float4*>(g_coef);
    float4 A = cf[c4];
    float4 B = cf[16 + c4];
    int row0 = gid >> 4;
    int rstride = (gridDim.x * blockDim.x) >> 4;
    float4* o4 = reinterpret_cast<float4*>(out);
    for (int r = row0; r < n_out; r += rstride) {
        size_t idx = (size_t)r * 16 + c4;
        float4 v = o4[idx];
        float4 y;
        y.x = fmaf(v.x, A.x, B.x);
        y.y = fmaf(v.y, A.y, B.y);
        y.z = fmaf(v.z, A.z, B.z);
        y.w = fmaf(v.w, A.w, B.w);
        y.x = fmaxf(y.x, LEAK * y.x);
        y.y = fmaxf(y.y, LEAK * y.y);
        y.z = fmaxf(y.z, LEAK * y.z);
        y.w = fmaxf(y.w, LEAK * y.w);
        o4[idx] = y;
    }
}

// ---- launch ----------------------------------------------------------------
extern "C" void kernel_launch(void* const* d_in, const int* in_sizes, int n_in,
                              void* d_out, int out_size)
{
    const float* feat    = (const float*)d_in[0];
    const float* weight  = (const float*)d_in[1];
    // d_in[2] = bias: cancelled exactly by BN mean subtraction
    const float* gamma   = (const float*)d_in[3];
    const float* beta    = (const float*)d_in[4];
    const int*   out_idx = (const int*)d_in[5];
    const int*   kern_idx= (const int*)d_in[6];
    int n_rows = in_sizes[0] / CIN;
    int n_out  = out_size / COUT;
    float* out = (float*)d_out;

    cudaMemsetAsync(d_out, 0, (size_t)out_size * sizeof(float));
    hist_kernel<<<HB, 256>>>(kern_idx, n_rows);
    scan_kernel<<<1, 4 * HB>>>(n_rows);
    scatter_kernel<<<HB, 256>>>(kern_idx, n_rows);
    conv_scatter<<<CONV_BLOCKS, 256>>>(feat, weight, out_idx, out, n_rows);  // 5th launch -> ncu slot
    stats_kernel<<<STATS_BLOCKS, 256>>>(out, n_out);
    coef_kernel<<<1, 128>>>(gamma, beta, n_out);
    norm_kernel<<<1184, 256>>>(out, n_out);
}

// round 8
// speedup vs baseline: 1.8399x; 1.8399x over previous
#include <cuda_runtime.h>
#include <cstdint>

#define CIN   32
#define COUT  64
#define EPS   1e-4f
#define LEAK  0.333f

#define HB           256
#define N_MAX        1600000
#define CONV_BLOCKS  592           // 148 SMs * 4 blocks of 128 = one wave
#define STATS_BLOCKS 1184

__device__ int   g_blockhist[4 * HB];
__device__ int   g_blockoff[4 * HB];
__device__ int   g_bucket_start[5];
__device__ int   g_perm[N_MAX];
__device__ float g_partials[STATS_BLOCKS * 128];
__device__ float g_tot[128];
__device__ float g_coef[128];

// ---- packed f32x2 helpers (sm_103a) ---------------------------------------
__device__ __forceinline__ unsigned long long packpair(float lo, float hi) {
    unsigned long long r;
    asm("mov.b64 %0, {%1, %2};" : "=l"(r) : "f"(lo), "f"(hi));
    return r;
}
__device__ __forceinline__ unsigned long long ffma2(unsigned long long a,
                                                    unsigned long long b,
                                                    unsigned long long c) {
    unsigned long long d;
    asm("fma.rn.f32x2 %0, %1, %2, %3;" : "=l"(d) : "l"(a), "l"(b), "l"(c));
    return d;
}
__device__ __forceinline__ void unpack2(unsigned long long v, float& lo, float& hi) {
    asm("mov.b64 {%0, %1}, %2;" : "=f"(lo), "=f"(hi) : "l"(v));
}

// ---- sort pass 1: per-block histogram of kern_idx --------------------------
__global__ __launch_bounds__(256) void hist_kernel(const int* __restrict__ kern_idx,
                                                   int n_rows)
{
    __shared__ int cnt[4];
    if (threadIdx.x < 4) cnt[threadIdx.x] = 0;
    __syncthreads();
    int chunk = (n_rows + HB - 1) / HB;
    int i0 = blockIdx.x * chunk;
    int i1 = min(i0 + chunk, n_rows);
    int c[4] = {0, 0, 0, 0};
    for (int i = i0 + threadIdx.x; i < i1; i += 256) c[kern_idx[i]]++;
    #pragma unroll
    for (int kk = 0; kk < 4; kk++)
        if (c[kk]) atomicAdd(&cnt[kk], c[kk]);
    __syncthreads();
    if (threadIdx.x < 4)
        g_blockhist[threadIdx.x * HB + blockIdx.x] = cnt[threadIdx.x];
}

// ---- sort pass 2: segmented scan -> per-block offsets + bucket starts ------
__global__ void scan_kernel(int n_rows)
{
    __shared__ int sh[4 * HB];
    int t = threadIdx.x;            // 0..1023, t = k*256 + b
    int orig = g_blockhist[t];
    sh[t] = orig;
    __syncthreads();
    for (int s = 1; s < HB; s <<= 1) {
        int add = ((t & (HB - 1)) >= s) ? sh[t - s] : 0;
        __syncthreads();
        sh[t] += add;
        __syncthreads();
    }
    int k = t >> 8;
    int kbase = 0;
    for (int kk = 0; kk < k; kk++) kbase += sh[kk * HB + HB - 1];
    g_blockoff[t] = kbase + (sh[t] - orig);
    if ((t & (HB - 1)) == 0) g_bucket_start[k] = kbase;
    if (t == 0) g_bucket_start[4] = n_rows;
}

// ---- sort pass 3: scatter row indices into buckets -------------------------
__global__ __launch_bounds__(256) void scatter_kernel(const int* __restrict__ kern_idx,
                                                      int n_rows)
{
    __shared__ int scur[4];
    if (threadIdx.x < 4)
        scur[threadIdx.x] = g_blockoff[threadIdx.x * HB + blockIdx.x];
    __syncthreads();
    int chunk = (n_rows + HB - 1) / HB;
    int i0 = blockIdx.x * chunk;
    int i1 = min(i0 + chunk, n_rows);
    int iters = (i1 > i0) ? ((i1 - i0 + 255) >> 8) : 0;
    int lane = threadIdx.x & 31;
    for (int it = 0; it < iters; it++) {
        int i = i0 + it * 256 + threadIdx.x;
        int k = (i < i1) ? kern_idx[i] : -1;
        #pragma unroll
        for (int kk = 0; kk < 4; kk++) {
            unsigned mask = __ballot_sync(0xFFFFFFFFu, k == kk);
            if (k == kk) {
                int leader = __ffs(mask) - 1;
                int base = 0;
                if (lane == leader) base = atomicAdd(&scur[kk], __popc(mask));
                base = __shfl_sync(mask, base, leader);
                int pos = base + __popc(mask & ((1u << lane) - 1));
                g_perm[pos] = i;
            }
        }
    }
}

// ---- conv: warp-per-row, j-pair packed weights in regs, cp.async ring ------
// lane l owns channels {2l,2l+1}. Per row: 1 LDGSTS (row->smem ring, MLP=4),
// 8 broadcast LDS.128, 32 FFMA2 (4 chains), 1 RED.64 (256B contiguous).
// No shfl, no pack in the hot loop.
__global__ __launch_bounds__(128, 4) void conv_scatter(
    const float* __restrict__ feat,
    const float* __restrict__ weight,
    const int*   __restrict__ out_idx,
    float*       __restrict__ out)
{
    __shared__ ulonglong2 ring[4][4][8];   // [warp][stage][t]
    int lane   = threadIdx.x & 31;
    int wlocal = threadIdx.x >> 5;
    int gw     = (blockIdx.x * blockDim.x + threadIdx.x) >> 5;
    int k      = gw & 3;
    int wslot  = gw >> 2;
    int nwb    = (gridDim.x * blockDim.x) >> 7;   // warps per bucket

    // j-pair packed weights: w0[u] = (w[2u][c0], w[2u+1][c0]) etc.
    int c0 = 2 * lane;
    unsigned long long w0[16], w1[16];
    #pragma unroll
    for (int u = 0; u < 16; u++) {
        const float* r0p = weight + (size_t)(k * 32 + 2 * u) * COUT;
        const float* r1p = weight + (size_t)(k * 32 + 2 * u + 1) * COUT;
        w0[u] = packpair(r0p[c0],     r1p[c0]);
        w1[u] = packpair(r0p[c0 + 1], r1p[c0 + 1]);
    }

    int start = g_bucket_start[k];
    int end   = g_bucket_start[k + 1];
    if (start >= end) return;

    int p0 = start + wslot;
    // index queue: ii[j] = input row for iteration m+j
    int ii[6];
    #pragma unroll
    for (int j = 0; j < 6; j++) {
        int pc = p0 + j * nwb;
        pc = pc < end ? pc : end - 1;
        ii[j] = g_perm[pc];
    }
    int oq0 = out_idx[ii[0]];
    int oq1 = out_idx[ii[1]];

    unsigned sbase =
        (unsigned)__cvta_generic_to_shared(&ring[wlocal][0][0]);

    // prologue: fill stages 0..2 (rows m=0,1,2); all 32 lanes copy 4B each
    #pragma unroll
    for (int s = 0; s < 3; s++) {
        const float* g = feat + (size_t)ii[s] * CIN + lane;
        asm volatile("cp.async.ca.shared.global [%0], [%1], 4;"
                     :: "r"(sbase + s * 128 + lane * 4), "l"(g));
        asm volatile("cp.async.commit_group;");
    }

    int m = 0;
    for (int p = p0; p < end; p += nwb, m++) {
        // prefetch perm for row m+6 (2-iteration cover for DRAM latency)
        int pc = p + 6 * nwb;
        pc = pc < end ? pc : end - 1;
        int i_new = g_perm[pc];
        int o_new = out_idx[ii[2]];          // out row for iteration m+2

        // issue feat copy for row m+3 into stage (m+3)&3
        {
            int s = (m + 3) & 3;
            const float* g = feat + (size_t)ii[3] * CIN + lane;
            asm volatile("cp.async.ca.shared.global [%0], [%1], 4;"
                         :: "r"(sbase + s * 128 + lane * 4), "l"(g));
            asm volatile("cp.async.commit_group;");
        }
        asm volatile("cp.async.wait_group 3;");
        __syncwarp();

        const ulonglong2* q = ring[wlocal][m & 3];
        unsigned long long a0 = 0ull, a1 = 0ull, b0 = 0ull, b1 = 0ull;
        #pragma unroll
        for (int t = 0; t < 8; t++) {
            ulonglong2 qv = q[t];            // broadcast LDS.128: (f4t,f4t+1),(f4t+2,f4t+3)
            a0 = ffma2(w0[2 * t],     qv.x, a0);
            a1 = ffma2(w0[2 * t + 1], qv.y, a1);
            b0 = ffma2(w1[2 * t],     qv.x, b0);
            b1 = ffma2(w1[2 * t + 1], qv.y, b1);
        }
        unsigned long long as, bs;
        asm("add.rn.f32x2 %0, %1, %2;" : "=l"(as) : "l"(a0), "l"(a1));
        asm("add.rn.f32x2 %0, %1, %2;" : "=l"(bs) : "l"(b0), "l"(b1));
        float alo, ahi, blo, bhi;
        unpack2(as, alo, ahi);
        unpack2(bs, blo, bhi);
        atomicAdd(reinterpret_cast<float2*>(out + (size_t)oq0 * COUT + c0),
                  make_float2(alo + ahi, blo + bhi));   // 256B contiguous RED.64

        // rotate queues
        ii[0] = ii[1]; ii[1] = ii[2]; ii[2] = ii[3];
        ii[3] = ii[4]; ii[4] = ii[5]; ii[5] = i_new;
        oq0 = oq1; oq1 = o_new;
    }
    asm volatile("cp.async.wait_group 0;");   // drain before exit
}

// ---- stats: per-channel sum / sumsq partials -------------------------------
__global__ __launch_bounds__(256) void stats_kernel(const float* __restrict__ out,
                                                    int n_out)
{
    __shared__ float sh[128];
    if (threadIdx.x < 128) sh[threadIdx.x] = 0.f;
    __syncthreads();

    int gid = blockIdx.x * blockDim.x + threadIdx.x;
    int c4 = threadIdx.x & 15;
    int row0 = gid >> 4;
    int rstride = (gridDim.x * blockDim.x) >> 4;
    const float4* o4 = reinterpret_cast<const float4*>(out);

    float4 s = make_float4(0.f, 0.f, 0.f, 0.f);
    float4 q = make_float4(0.f, 0.f, 0.f, 0.f);
    for (int r = row0; r < n_out; r += rstride) {
        float4 v = o4[(size_t)r * 16 + c4];
        s.x += v.x; s.y += v.y; s.z += v.z; s.w += v.w;
        q.x += v.x * v.x; q.y += v.y * v.y; q.z += v.z * v.z; q.w += v.w * v.w;
    }
    s.x += __shfl_down_sync(0xFFFFFFFFu, s.x, 16);
    s.y += __shfl_down_sync(0xFFFFFFFFu, s.y, 16);
    s.z += __shfl_down_sync(0xFFFFFFFFu, s.z, 16);
    s.w += __shfl_down_sync(0xFFFFFFFFu, s.w, 16);
    q.x += __shfl_down_sync(0xFFFFFFFFu, q.x, 16);
    q.y += __shfl_down_sync(0xFFFFFFFFu, q.y, 16);
    q.z += __shfl_down_sync(0xFFFFFFFFu, q.z, 16);
    q.w += __shfl_down_sync(0xFFFFFFFFu, q.w, 16);

    if ((threadIdx.x & 31) < 16) {
        atomicAdd(&sh[c4 * 4 + 0], s.x);
        atomicAdd(&sh[c4 * 4 + 1], s.y);
        atomicAdd(&sh[c4 * 4 + 2], s.z);
        atomicAdd(&sh[c4 * 4 + 3], s.w);
        atomicAdd(&sh[64 + c4 * 4 + 0], q.x);
        atomicAdd(&sh[64 + c4 * 4 + 1], q.y);
        atomicAdd(&sh[64 + c4 * 4 + 2], q.z);
        atomicAdd(&sh[64 + c4 * 4 + 3], q.w);
    }
    __syncthreads();
    if (threadIdx.x < 128)
        g_partials[blockIdx.x * 128 + threadIdx.x] = sh[threadIdx.x];
}

// ---- reduce partials (parallel over 128 stat slots) ------------------------
__global__ __launch_bounds__(256) void reduce_kernel()
{
    int s = blockIdx.x;                 // 0..127
    float acc = 0.f;
    for (int b = threadIdx.x; b < STATS_BLOCKS; b += 256)
        acc += g_partials[b * 128 + s];
    __shared__ float sh[256];
    sh[threadIdx.x] = acc;
    __syncthreads();
    for (int st = 128; st > 0; st >>= 1) {
        if (threadIdx.x < st) sh[threadIdx.x] += sh[threadIdx.x + st];
        __syncthreads();
    }
    if (threadIdx.x == 0) g_tot[s] = sh[0];
}

// ---- coef: per-channel A,B -------------------------------------------------
__global__ void coef2_kernel(const float* __restrict__ gamma,
                             const float* __restrict__ beta,
                             int n_out)
{
    int t = threadIdx.x;   // 0..63
    float inv_n = 1.0f / (float)n_out;
    float mean = g_tot[t] * inv_n;
    float var  = g_tot[64 + t] * inv_n - mean * mean;
    float A = gamma[t] * rsqrtf(var + EPS);
    g_coef[t] = A;
    g_coef[64 + t] = beta[t] - mean * A;
}

// ---- norm + leaky relu (in place, at DRAM roofline) ------------------------
__global__ __launch_bounds__(256) void norm_kernel(float* __restrict__ out, int n_out)
{
    int gid = blockIdx.x * blockDim.x + threadIdx.x;
    int c4 = threadIdx.x & 15;
    const float4* cf = reinterpret_cast<const float4*>(g_coef);
    float4 A = cf[c4];
    float4 B = cf[16 + c4];
    int row0 = gid >> 4;
    int rstride = (gridDim.x * blockDim.x) >> 4;
    float4* o4 = reinterpret_cast<float4*>(out);
    for (int r = row0; r < n_out; r += rstride) {
        size_t idx = (size_t)r * 16 + c4;
        float4 v = o4[idx];
        float4 y;
        y.x = fmaf(v.x, A.x, B.x);
        y.y = fmaf(v.y, A.y, B.y);
        y.z = fmaf(v.z, A.z, B.z);
        y.w = fmaf(v.w, A.w, B.w);
        y.x = fmaxf(y.x, LEAK * y.x);
        y.y = fmaxf(y.y, LEAK * y.y);
        y.z = fmaxf(y.z, LEAK * y.z);
        y.w = fmaxf(y.w, LEAK * y.w);
        o4[idx] = y;
    }
}

// ---- launch ----------------------------------------------------------------
extern "C" void kernel_launch(void* const* d_in, const int* in_sizes, int n_in,
                              void* d_out, int out_size)
{
    const float* feat    = (const float*)d_in[0];
    const float* weight  = (const float*)d_in[1];
    // d_in[2] = bias: cancelled exactly by BN mean subtraction
    const float* gamma   = (const float*)d_in[3];
    const float* beta    = (const float*)d_in[4];
    const int*   out_idx = (const int*)d_in[5];
    const int*   kern_idx= (const int*)d_in[6];
    int n_rows = in_sizes[0] / CIN;
    int n_out  = out_size / COUT;
    float* out = (float*)d_out;

    cudaMemsetAsync(d_out, 0, (size_t)out_size * sizeof(float));
    hist_kernel<<<HB, 256>>>(kern_idx, n_rows);
    scan_kernel<<<1, 4 * HB>>>(n_rows);
    scatter_kernel<<<HB, 256>>>(kern_idx, n_rows);
    conv_scatter<<<CONV_BLOCKS, 128>>>(feat, weight, out_idx, out);  // 5th launch -> ncu slot
    stats_kernel<<<STATS_BLOCKS, 256>>>(out, n_out);
    reduce_kernel<<<128, 256>>>();
    coef2_kernel<<<1, 64>>>(gamma, beta, n_out);
    norm_kernel<<<1184, 256>>>(out, n_out);
}

// round 10
// speedup vs baseline: 1.9313x; 1.0497x over previous
#include <cuda_runtime.h>
#include <cstdint>

#define CIN   32
#define COUT  64
#define EPS   1e-4f
#define LEAK  0.333f

#define HB           256
#define N_MAX        1600000
#define CONV_BLOCKS  592           // 148 SMs * 4 blocks of 128
#define STATS_BLOCKS 1184

__device__ int   g_blockhist[4 * HB];
__device__ int   g_blockoff[4 * HB];
__device__ int   g_bucket_start[5];
__device__ int   g_perm[N_MAX];
__device__ float g_partials[STATS_BLOCKS * 128];
__device__ float g_tot[128];
__device__ float g_coef[128];

// ---- packed f32x2 helpers (sm_103a) ---------------------------------------
__device__ __forceinline__ unsigned long long packpair(float lo, float hi) {
    unsigned long long r;
    asm("mov.b64 %0, {%1, %2};" : "=l"(r) : "f"(lo), "f"(hi));
    return r;
}
__device__ __forceinline__ unsigned long long ffma2(unsigned long long a,
                                                    unsigned long long b,
                                                    unsigned long long c) {
    unsigned long long d;
    asm("fma.rn.f32x2 %0, %1, %2, %3;" : "=l"(d) : "l"(a), "l"(b), "l"(c));
    return d;
}
__device__ __forceinline__ void unpack2(unsigned long long v, float& lo, float& hi) {
    asm("mov.b64 {%0, %1}, %2;" : "=f"(lo), "=f"(hi) : "l"(v));
}

// ---- sort pass 1: per-block histogram of kern_idx --------------------------
__global__ __launch_bounds__(256) void hist_kernel(const int* __restrict__ kern_idx,
                                                   int n_rows)
{
    __shared__ int cnt[4];
    if (threadIdx.x < 4) cnt[threadIdx.x] = 0;
    __syncthreads();
    int chunk = (n_rows + HB - 1) / HB;
    int i0 = blockIdx.x * chunk;
    int i1 = min(i0 + chunk, n_rows);
    int c[4] = {0, 0, 0, 0};
    for (int i = i0 + threadIdx.x; i < i1; i += 256) c[kern_idx[i]]++;
    #pragma unroll
    for (int kk = 0; kk < 4; kk++)
        if (c[kk]) atomicAdd(&cnt[kk], c[kk]);
    __syncthreads();
    if (threadIdx.x < 4)
        g_blockhist[threadIdx.x * HB + blockIdx.x] = cnt[threadIdx.x];
}

// ---- sort pass 2: segmented scan -> per-block offsets + bucket starts ------
__global__ void scan_kernel(int n_rows)
{
    __shared__ int sh[4 * HB];
    int t = threadIdx.x;            // 0..1023, t = k*256 + b
    int orig = g_blockhist[t];
    sh[t] = orig;
    __syncthreads();
    for (int s = 1; s < HB; s <<= 1) {
        int add = ((t & (HB - 1)) >= s) ? sh[t - s] : 0;
        __syncthreads();
        sh[t] += add;
        __syncthreads();
    }
    int k = t >> 8;
    int kbase = 0;
    for (int kk = 0; kk < k; kk++) kbase += sh[kk * HB + HB - 1];
    g_blockoff[t] = kbase + (sh[t] - orig);
    if ((t & (HB - 1)) == 0) g_bucket_start[k] = kbase;
    if (t == 0) g_bucket_start[4] = n_rows;
}

// ---- sort pass 3: scatter row indices into buckets -------------------------
__global__ __launch_bounds__(256) void scatter_kernel(const int* __restrict__ kern_idx,
                                                      int n_rows)
{
    __shared__ int scur[4];
    if (threadIdx.x < 4)
        scur[threadIdx.x] = g_blockoff[threadIdx.x * HB + blockIdx.x];
    __syncthreads();
    int chunk = (n_rows + HB - 1) / HB;
    int i0 = blockIdx.x * chunk;
    int i1 = min(i0 + chunk, n_rows);
    int iters = (i1 > i0) ? ((i1 - i0 + 255) >> 8) : 0;
    int lane = threadIdx.x & 31;
    for (int it = 0; it < iters; it++) {
        int i = i0 + it * 256 + threadIdx.x;
        int k = (i < i1) ? kern_idx[i] : -1;
        #pragma unroll
        for (int kk = 0; kk < 4; kk++) {
            unsigned mask = __ballot_sync(0xFFFFFFFFu, k == kk);
            if (k == kk) {
                int leader = __ffs(mask) - 1;
                int base = 0;
                if (lane == leader) base = atomicAdd(&scur[kk], __popc(mask));
                base = __shfl_sync(mask, base, leader);
                int pos = base + __popc(mask & ((1u << lane) - 1));
                g_perm[pos] = i;
            }
        }
    }
}

// ---- conv: warp-per-ROW-PAIR, j-pair packed weights in regs ----------------
// lane l owns channels {2l,2l+1}. Per iteration (2 rows): 1 LDGSTS (8B/lane,
// both rows), 16 broadcast LDS.128, 64 FFMA2 in 8 independent chains,
// 2 RED.64. One wait/sync per 2 rows.
__global__ __launch_bounds__(128, 4) void conv_scatter(
    const float* __restrict__ feat,
    const float* __restrict__ weight,
    const int*   __restrict__ out_idx,
    float*       __restrict__ out)
{
    __shared__ ulonglong2 ring[4][4][16];   // [warp][stage][2 rows x 8]
    int lane   = threadIdx.x & 31;
    int wlocal = threadIdx.x >> 5;
    int gw     = (blockIdx.x * blockDim.x + threadIdx.x) >> 5;
    int k      = gw & 3;
    int wslot  = gw >> 2;
    int nwb    = (gridDim.x * blockDim.x) >> 7;   // warps per bucket

    // j-pair packed weights for lane's two channels
    int c0 = 2 * lane;
    unsigned long long w0[16], w1[16];
    #pragma unroll
    for (int u = 0; u < 16; u++) {
        const float* r0p = weight + (size_t)(k * 32 + 2 * u) * COUT;
        const float* r1p = weight + (size_t)(k * 32 + 2 * u + 1) * COUT;
        w0[u] = packpair(r0p[c0],     r1p[c0]);
        w1[u] = packpair(r0p[c0 + 1], r1p[c0 + 1]);
    }

    int start = g_bucket_start[k];
    int end   = g_bucket_start[k + 1];
    if (start >= end) return;

    int p0 = start + wslot;
    int step = 2 * nwb;                       // per-iteration stride (row pair)

    // index queue: ii[2t], ii[2t+1] = rows of iteration m+t (t=0..3), clamped
    int ii[8];
    #pragma unroll
    for (int j = 0; j < 8; j++) {
        int pc = p0 + ((j >> 1) * 2 + (j & 1)) * nwb;
        pc = pc < end ? pc : end - 1;
        ii[j] = g_perm[pc];
    }
    // out rows for iterations m and m+1
    int oq[4];
    oq[0] = out_idx[ii[0]]; oq[1] = out_idx[ii[1]];
    oq[2] = out_idx[ii[2]]; oq[3] = out_idx[ii[3]];

    unsigned sbase = (unsigned)__cvta_generic_to_shared(&ring[wlocal][0][0]);
    int half = lane >> 4;                     // 0: row a, 1: row b
    int hoff = (lane & 15) * 2;               // float offset within row

    // prologue: fill stages 0..2 (iterations 0,1,2)
    #pragma unroll
    for (int s = 0; s < 3; s++) {
        const float* g = feat + (size_t)ii[2 * s + half] * CIN + hoff;
        asm volatile("cp.async.ca.shared.global [%0], [%1], 8;"
                     :: "r"(sbase + s * 256 + lane * 8), "l"(g));
        asm volatile("cp.async.commit_group;");
    }

    int m = 0;
    for (int p = p0; p < end; p += step, m++) {
        // prefetch perm rows of iteration m+4 (cover ~4 iterations)
        int pa = p + 8 * nwb; pa = pa < end ? pa : end - 1;
        int pb = p + 9 * nwb; pb = pb < end ? pb : end - 1;
        int ia_new = g_perm[pa];
        int ib_new = g_perm[pb];
        // out rows of iteration m+2 (perm values already in queue)
        int oa_new = out_idx[ii[4]];
        int ob_new = out_idx[ii[5]];

        // fill stage for iteration m+3 (rows ii[6], ii[7])
        {
            int s = (m + 3) & 3;
            const float* g = feat + (size_t)ii[6 + half] * CIN + hoff;
            asm volatile("cp.async.ca.shared.global [%0], [%1], 8;"
                         :: "r"(sbase + s * 256 + lane * 8), "l"(g));
            asm volatile("cp.async.commit_group;");
        }
        asm volatile("cp.async.wait_group 3;");
        __syncwarp();

        const ulonglong2* q = ring[wlocal][m & 3];
        unsigned long long a0 = 0ull, a1 = 0ull, b0 = 0ull, b1 = 0ull;  // row a
        unsigned long long d0 = 0ull, d1 = 0ull, e0 = 0ull, e1 = 0ull;  // row b
        #pragma unroll
        for (int t = 0; t < 8; t++) {
            ulonglong2 qa = q[t];
            ulonglong2 qb = q[8 + t];
            a0 = ffma2(w0[2 * t],     qa.x, a0);
            a1 = ffma2(w0[2 * t + 1], qa.y, a1);
            b0 = ffma2(w1[2 * t],     qa.x, b0);
            b1 = ffma2(w1[2 * t + 1], qa.y, b1);
            d0 = ffma2(w0[2 * t],     qb.x, d0);
            d1 = ffma2(w0[2 * t + 1], qb.y, d1);
            e0 = ffma2(w1[2 * t],     qb.x, e0);
            e1 = ffma2(w1[2 * t + 1], qb.y, e1);
        }
        unsigned long long as, bs, ds, es;
        asm("add.rn.f32x2 %0, %1, %2;" : "=l"(as) : "l"(a0), "l"(a1));
        asm("add.rn.f32x2 %0, %1, %2;" : "=l"(bs) : "l"(b0), "l"(b1));
        asm("add.rn.f32x2 %0, %1, %2;" : "=l"(ds) : "l"(d0), "l"(d1));
        asm("add.rn.f32x2 %0, %1, %2;" : "=l"(es) : "l"(e0), "l"(e1));
        float x0, x1, y0, y1;
        unpack2(as, x0, x1); unpack2(bs, y0, y1);
        atomicAdd(reinterpret_cast<float2*>(out + (size_t)oq[0] * COUT + c0),
                  make_float2(x0 + x1, y0 + y1));
        if (p + nwb < end) {                      // guard tail row
            unpack2(ds, x0, x1); unpack2(es, y0, y1);
            atomicAdd(reinterpret_cast<float2*>(out + (size_t)oq[1] * COUT + c0),
                      make_float2(x0 + x1, y0 + y1));
        }

        // rotate queues by one iteration (2 entries)
        ii[0] = ii[2]; ii[1] = ii[3]; ii[2] = ii[4]; ii[3] = ii[5];
        ii[4] = ii[6]; ii[5] = ii[7]; ii[6] = ia_new; ii[7] = ib_new;
        oq[0] = oq[2]; oq[1] = oq[3]; oq[2] = oa_new; oq[3] = ob_new;
    }
    asm volatile("cp.async.wait_group 0;");   // drain before exit
}

// ---- stats: per-channel sum / sumsq partials -------------------------------
__global__ __launch_bounds__(256) void stats_kernel(const float* __restrict__ out,
                                                    int n_out)
{
    __shared__ float sh[128];
    if (threadIdx.x < 128) sh[threadIdx.x] = 0.f;
    __syncthreads();

    int gid = blockIdx.x * blockDim.x + threadIdx.x;
    int c4 = threadIdx.x & 15;
    int row0 = gid >> 4;
    int rstride = (gridDim.x * blockDim.x) >> 4;
    const float4* o4 = reinterpret_cast<const float4*>(out);

    float4 s = make_float4(0.f, 0.f, 0.f, 0.f);
    float4 q = make_float4(0.f, 0.f, 0.f, 0.f);
    for (int r = row0; r < n_out; r += rstride) {
        float4 v = o4[(size_t)r * 16 + c4];
        s.x += v.x; s.y += v.y; s.z += v.z; s.w += v.w;
        q.x += v.x * v.x; q.y += v.y * v.y; q.z += v.z * v.z; q.w += v.w * v.w;
    }
    s.x += __shfl_down_sync(0xFFFFFFFFu, s.x, 16);
    s.y += __shfl_down_sync(0xFFFFFFFFu, s.y, 16);
    s.z += __shfl_down_sync(0xFFFFFFFFu, s.z, 16);
    s.w += __shfl_down_sync(0xFFFFFFFFu, s.w, 16);
    q.x += __shfl_down_sync(0xFFFFFFFFu, q.x, 16);
    q.y += __shfl_down_sync(0xFFFFFFFFu, q.y, 16);
    q.z += __shfl_down_sync(0xFFFFFFFFu, q.z, 16);
    q.w += __shfl_down_sync(0xFFFFFFFFu, q.w, 16);

    if ((threadIdx.x & 31) < 16) {
        atomicAdd(&sh[c4 * 4 + 0], s.x);
        atomicAdd(&sh[c4 * 4 + 1], s.y);
        atomicAdd(&sh[c4 * 4 + 2], s.z);
        atomicAdd(&sh[c4 * 4 + 3], s.w);
        atomicAdd(&sh[64 + c4 * 4 + 0], q.x);
        atomicAdd(&sh[64 + c4 * 4 + 1], q.y);
        atomicAdd(&sh[64 + c4 * 4 + 2], q.z);
        atomicAdd(&sh[64 + c4 * 4 + 3], q.w);
    }
    __syncthreads();
    if (threadIdx.x < 128)
        g_partials[blockIdx.x * 128 + threadIdx.x] = sh[threadIdx.x];
}

// ---- reduce partials (parallel over 128 stat slots) ------------------------
__global__ __launch_bounds__(256) void reduce_kernel()
{
    int s = blockIdx.x;                 // 0..127
    float acc = 0.f;
    for (int b = threadIdx.x; b < STATS_BLOCKS; b += 256)
        acc += g_partials[b * 128 + s];
    __shared__ float sh[256];
    sh[threadIdx.x] = acc;
    __syncthreads();
    for (int st = 128; st > 0; st >>= 1) {
        if (threadIdx.x < st) sh[threadIdx.x] += sh[threadIdx.x + st];
        __syncthreads();
    }
    if (threadIdx.x == 0) g_tot[s] = sh[0];
}

// ---- coef: per-channel A,B -------------------------------------------------
__global__ void coef2_kernel(const float* __restrict__ gamma,
                             const float* __restrict__ beta,
                             int n_out)
{
    int t = threadIdx.x;   // 0..63
    float inv_n = 1.0f / (float)n_out;
    float mean = g_tot[t] * inv_n;
    float var  = g_tot[64 + t] * inv_n - mean * mean;
    float A = gamma[t] * rsqrtf(var + EPS);
    g_coef[t] = A;
    g_coef[64 + t] = beta[t] - mean * A;
}

// ---- norm + leaky relu (in place, at DRAM roofline) ------------------------
__global__ __launch_bounds__(256) void norm_kernel(float* __restrict__ out, int n_out)
{
    int gid = blockIdx.x * blockDim.x + threadIdx.x;
    int c4 = threadIdx.x & 15;
    const float4* cf = reinterpret_cast<const float4*>(g_coef);
    float4 A = cf[c4];
    float4 B = cf[16 + c4];
    int row0 = gid >> 4;
    int rstride = (gridDim.x * blockDim.x) >> 4;
    float4* o4 = reinterpret_cast<float4*>(out);
    for (int r = row0; r < n_out; r += rstride) {
        size_t idx = (size_t)r * 16 + c4;
        float4 v = o4[idx];
        float4 y;
        y.x = fmaf(v.x, A.x, B.x);
        y.y = fmaf(v.y, A.y, B.y);
        y.z = fmaf(v.z, A.z, B.z);
        y.w = fmaf(v.w, A.w, B.w);
        y.x = fmaxf(y.x, LEAK * y.x);
        y.y = fmaxf(y.y, LEAK * y.y);
        y.z = fmaxf(y.z, LEAK * y.z);
        y.w = fmaxf(y.w, LEAK * y.w);
        o4[idx] = y;
    }
}

// ---- launch ----------------------------------------------------------------
extern "C" void kernel_launch(void* const* d_in, const int* in_sizes, int n_in,
                              void* d_out, int out_size)
{
    const float* feat    = (const float*)d_in[0];
    const float* weight  = (const float*)d_in[1];
    // d_in[2] = bias: cancelled exactly by BN mean subtraction
    const float* gamma   = (const float*)d_in[3];
    const float* beta    = (const float*)d_in[4];
    const int*   out_idx = (const int*)d_in[5];
    const int*   kern_idx= (const int*)d_in[6];
    int n_rows = in_sizes[0] / CIN;
    int n_out  = out_size / COUT;
    float* out = (float*)d_out;

    cudaMemsetAsync(d_out, 0, (size_t)out_size * sizeof(float));
    hist_kernel<<<HB, 256>>>(kern_idx, n_rows);
    scan_kernel<<<1, 4 * HB>>>(n_rows);
    scatter_kernel<<<HB, 256>>>(kern_idx, n_rows);
    conv_scatter<<<CONV_BLOCKS, 128>>>(feat, weight, out_idx, out);  // 5th launch -> ncu slot
    stats_kernel<<<STATS_BLOCKS, 256>>>(out, n_out);
    reduce_kernel<<<128, 256>>>();
    coef2_kernel<<<1, 64>>>(gamma, beta, n_out);
    norm_kernel<<<1184, 256>>>(out, n_out);
}